// round 9
// baseline (speedup 1.0000x reference)
#include <cuda_runtime.h>
#include <cstdint>

#define Tn 128
#define Bn 8
#define Sn 512
#define CLUSTER 16
#define ROWS_PER_CTA 32
#define NTHREADS 512
#define NWARPS 16
#define HALF_ROWS 16
#define HALF_FLOATS (HALF_ROWS * Sn)     // 8192 floats = 32 KB
#define HALF_BYTES (HALF_FLOATS * 4)
#define NBUF 6
#define SMEM_DYN (NBUF * HALF_BYTES)     // 196608 B
#define VEX_BYTES (CLUSTER * 128)

#define LOG2E 1.4426950408889634f
#define LN2   0.6931471805599453f

__device__ __forceinline__ float ex2f(float x) {
    float y; asm("ex2.approx.ftz.f32 %0, %1;" : "=f"(y) : "f"(x)); return y;
}
__device__ __forceinline__ float lg2f(float x) {
    float y; asm("lg2.approx.ftz.f32 %0, %1;" : "=f"(y) : "f"(x)); return y;
}
__device__ __forceinline__ void mbar_init(uint32_t mb, uint32_t count) {
    asm volatile("mbarrier.init.shared.b64 [%0], %1;" :: "r"(mb), "r"(count) : "memory");
}
__device__ __forceinline__ void mbar_expect_tx(uint32_t mb, uint32_t bytes) {
    asm volatile("mbarrier.arrive.expect_tx.shared.b64 _, [%0], %1;"
                 :: "r"(mb), "r"(bytes) : "memory");
}
__device__ __forceinline__ void mbar_arrive(uint32_t mb) {
    asm volatile("mbarrier.arrive.shared.b64 _, [%0];" :: "r"(mb) : "memory");
}
__device__ __forceinline__ void bulk_g2s(uint32_t dst, const float* src,
                                         uint32_t bytes, uint32_t mb) {
    asm volatile("cp.async.bulk.shared::cluster.global.mbarrier::complete_tx::bytes "
                 "[%0], [%1], %2, [%3];"
                 :: "r"(dst), "l"((const void*)src), "r"(bytes), "r"(mb) : "memory");
}
__device__ __forceinline__ void bulk_s2s(uint32_t dst_cluster, uint32_t src_cta,
                                         uint32_t bytes, uint32_t mb_cluster) {
    asm volatile("cp.async.bulk.shared::cluster.shared::cta.mbarrier::complete_tx::bytes "
                 "[%0], [%1], %2, [%3];"
                 :: "r"(dst_cluster), "r"(src_cta), "r"(bytes), "r"(mb_cluster) : "memory");
}
__device__ __forceinline__ void mbar_wait(uint32_t mb, uint32_t parity) {
    uint32_t done = 0;
    while (!done) {
        asm volatile(
            "{\n\t.reg .pred p;\n\t"
            "mbarrier.try_wait.parity.acquire.cta.shared::cta.b64 p, [%1], %2, 0x989680;\n\t"
            "selp.b32 %0, 1, 0, p;\n\t}"
            : "=r"(done) : "r"(mb), "r"(parity) : "memory");
    }
}
__device__ __forceinline__ uint32_t mapa32(uint32_t la, uint32_t ctaid) {
    uint32_t ra;
    asm("mapa.shared::cluster.u32 %0, %1, %2;" : "=r"(ra) : "r"(la), "r"(ctaid));
    return ra;
}
__device__ __forceinline__ uint32_t vex_parity(int p) {   // phase p >= 1
    return (uint32_t)(((p - 1) >> 1) & 1);
}

__global__ void __launch_bounds__(NTHREADS, 1)
viterbi_kernel(const float* __restrict__ theta, float* __restrict__ out)
{
    extern __shared__ float tiles[];                      // 6 halves; theta -> E in place
    __shared__ __align__(16) float Vb[2][Sn];
    __shared__ __align__(16) float mine[2][ROWS_PER_CTA];
    __shared__ float red[8];
    __shared__ __align__(8) unsigned long long tmbar[NBUF];
    __shared__ __align__(8) unsigned long long erbar[3];  // E ready, ring 3
    __shared__ __align__(8) unsigned long long mrbar[2];  // mine ready, ring 2
    __shared__ __align__(8) unsigned long long vexbar[2];

    const int tid  = threadIdx.x;
    const int lane = tid & 31;
    const int wid  = tid >> 5;

    uint32_t rank;
    asm("mov.u32 %0, %%cluster_ctarank;" : "=r"(rank));
    const int b = blockIdx.x >> 4;

    const size_t step_stride = (size_t)Bn * Sn * Sn;
    const float* base = theta + (size_t)b * Sn * Sn
                              + (size_t)rank * ROWS_PER_CTA * Sn;

    const uint32_t tiles_s = (uint32_t)__cvta_generic_to_shared(tiles);
    const uint32_t tmbar_s = (uint32_t)__cvta_generic_to_shared(&tmbar[0]);
    const uint32_t er_s    = (uint32_t)__cvta_generic_to_shared(&erbar[0]);
    const uint32_t mr_s    = (uint32_t)__cvta_generic_to_shared(&mrbar[0]);
    const uint32_t vex_s   = (uint32_t)__cvta_generic_to_shared(&vexbar[0]);
    const uint32_t mine_s  = (uint32_t)__cvta_generic_to_shared(&mine[0][0]);
    const uint32_t vb_s    = (uint32_t)__cvta_generic_to_shared(&Vb[0][0]);

    Vb[0][tid] = 0.0f;
    if (tid == 0) {
        #pragma unroll
        for (int s = 0; s < NBUF; ++s) mbar_init(tmbar_s + 8u * s, 1);
        #pragma unroll
        for (int s = 0; s < 3; ++s) mbar_init(er_s + 8u * s, 8);   // 8 producer warps
        mbar_init(mr_s,      8);                                    // 8 consumer warps
        mbar_init(mr_s + 8u, 8);
        mbar_init(vex_s,      1);
        mbar_init(vex_s + 8u, 1);
    }
    __syncthreads();
    asm volatile("fence.proxy.async.shared::cta;" ::: "memory");
    asm volatile("barrier.cluster.arrive.aligned;" ::: "memory");
    asm volatile("barrier.cluster.wait.aligned;"   ::: "memory");

    // prefetch steps 0..2 (all 6 half-buffers)
    if (tid == 0) {
        #pragma unroll
        for (int g = 0; g < 6; ++g) {
            mbar_expect_tx(tmbar_s + 8u * g, HALF_BYTES);
            bulk_g2s(tiles_s + (uint32_t)g * HALF_BYTES,
                     base + (size_t)(g >> 1) * step_stride + (size_t)(g & 1) * HALF_FLOATS,
                     HALF_BYTES, tmbar_s + 8u * g);
        }
    }

    if (wid < 8) {
        // ================= CONSUMER warps 0-7: dot + exchange =================
        const int half = wid >> 2;
        const int lr   = 4 * wid - HALF_ROWS * half;   // local row base within half

        #pragma unroll 1
        for (int t = 0; t < Tn; ++t) {
            if (wid == 0 && lane == 0)
                mbar_expect_tx(vex_s + 8u * (uint32_t)((t + 1) & 1), VEX_BYTES);
            if (t > 0)
                mbar_wait(vex_s + 8u * (uint32_t)(t & 1), vex_parity(t));

            const int pb = t & 1;
            const float M  = Vb[pb][0];
            const float nM = -M * LOG2E;

            // per-lane W = exp2((V-M)*log2e) for the 16 j's this lane uses
            const float4* vb4 = (const float4*)Vb[pb];
            float4 W[4];
            #pragma unroll
            for (int c = 0; c < 4; ++c) {
                float4 v = vb4[c * 32 + lane];
                W[c].x = ex2f(fmaf(v.x, LOG2E, nM));
                W[c].y = ex2f(fmaf(v.y, LOG2E, nM));
                W[c].z = ex2f(fmaf(v.z, LOG2E, nM));
                W[c].w = ex2f(fmaf(v.w, LOG2E, nM));
            }

            // wait E(t) converted
            mbar_wait(er_s + 8u * (uint32_t)(t % 3), (uint32_t)((t / 3) & 1));

            const float* eb = tiles + (2 * (t % 3) + half) * HALF_FLOATS + lr * Sn;
            const float4* r0 = (const float4*)(eb);
            const float4* r1 = (const float4*)(eb + Sn);
            const float4* r2 = (const float4*)(eb + 2 * Sn);
            const float4* r3 = (const float4*)(eb + 3 * Sn);

            float a0 = 0.f, a1 = 0.f, a2 = 0.f, a3 = 0.f;
            #pragma unroll
            for (int c = 0; c < 4; ++c) {
                const int idx = c * 32 + lane;
                const float4 w = W[c];
                float4 e0 = r0[idx], e1 = r1[idx], e2 = r2[idx], e3 = r3[idx];
                a0 = fmaf(e0.x, w.x, a0); a0 = fmaf(e0.y, w.y, a0);
                a0 = fmaf(e0.z, w.z, a0); a0 = fmaf(e0.w, w.w, a0);
                a1 = fmaf(e1.x, w.x, a1); a1 = fmaf(e1.y, w.y, a1);
                a1 = fmaf(e1.z, w.z, a1); a1 = fmaf(e1.w, w.w, a1);
                a2 = fmaf(e2.x, w.x, a2); a2 = fmaf(e2.y, w.y, a2);
                a2 = fmaf(e2.z, w.z, a2); a2 = fmaf(e2.w, w.w, a2);
                a3 = fmaf(e3.x, w.x, a3); a3 = fmaf(e3.y, w.y, a3);
                a3 = fmaf(e3.z, w.z, a3); a3 = fmaf(e3.w, w.w, a3);
            }
            #pragma unroll
            for (int o = 16; o > 0; o >>= 1) {
                a0 += __shfl_xor_sync(0xffffffffu, a0, o);
                a1 += __shfl_xor_sync(0xffffffffu, a1, o);
                a2 += __shfl_xor_sync(0xffffffffu, a2, o);
                a3 += __shfl_xor_sync(0xffffffffu, a3, o);
            }
            if (lane == 0) {
                mine[pb][4 * wid]     = fmaf(lg2f(a0), LN2, M);
                mine[pb][4 * wid + 1] = fmaf(lg2f(a1), LN2, M);
                mine[pb][4 * wid + 2] = fmaf(lg2f(a2), LN2, M);
                mine[pb][4 * wid + 3] = fmaf(lg2f(a3), LN2, M);
                mbar_arrive(mr_s + 8u * (uint32_t)pb);
            }

            if (wid == 0) {
                mbar_wait(mr_s + 8u * (uint32_t)pb, (uint32_t)((t >> 1) & 1));
                asm volatile("fence.proxy.async.shared::cta;" ::: "memory");
                if (lane < CLUSTER) {
                    const uint32_t dst = vb_s +
                        (uint32_t)(((t + 1) & 1) * Sn + rank * ROWS_PER_CTA) * 4u;
                    const uint32_t mb  = vex_s + 8u * (uint32_t)((t + 1) & 1);
                    bulk_s2s(mapa32(dst, lane),
                             mine_s + (uint32_t)pb * (ROWS_PER_CTA * 4),
                             ROWS_PER_CTA * 4, mapa32(mb, lane));
                }
            } else if (wid == 1) {
                mbar_wait(mr_s + 8u * (uint32_t)pb, (uint32_t)((t >> 1) & 1));
                if (lane == 0 && t + 3 < Tn) {
                    asm volatile("fence.proxy.async.shared::cta;" ::: "memory");
                    const int pre = t + 3;
                    #pragma unroll
                    for (int h = 0; h < 2; ++h) {
                        const int bi = (2 * pre + h) % NBUF;
                        mbar_expect_tx(tmbar_s + 8u * bi, HALF_BYTES);
                        bulk_g2s(tiles_s + (uint32_t)bi * HALF_BYTES,
                                 base + (size_t)pre * step_stride + (size_t)h * HALF_FLOATS,
                                 HALF_BYTES, tmbar_s + 8u * bi);
                    }
                }
            }
        }

        // ---- drain (consumers only: their parity tracking is exact) ----
        mbar_wait(vex_s + 8u * (uint32_t)(Tn & 1), vex_parity(Tn));

        // ---- final logsumexp by consumer warps only (256 thr, 2 states each) ----
        if (rank == 0) {
            const int fb = Tn & 1;
            const float M = Vb[fb][0];
            float e = ex2f((Vb[fb][tid] - M) * LOG2E)
                    + ex2f((Vb[fb][tid + 256] - M) * LOG2E);
            #pragma unroll
            for (int o = 16; o > 0; o >>= 1)
                e += __shfl_xor_sync(0xffffffffu, e, o);
            if (lane == 0) red[wid] = e;
            asm volatile("bar.sync 1, 256;" ::: "memory");   // consumers only
            if (tid == 0) {
                float s = 0.f;
                #pragma unroll
                for (int i = 0; i < 8; ++i) s += red[i];
                out[b] = fmaf(lg2f(s), LN2, M);
            }
        }
    } else {
        // ================= PRODUCER warps 8-15: theta -> E conversion =========
        const int pw    = wid - 8;
        const int phalf = pw >> 2;
        const int plr   = 4 * pw - HALF_ROWS * phalf;

        #pragma unroll 1
        for (int t = 0; t < Tn; ++t) {
            const int bi = (2 * t + phalf) % NBUF;
            mbar_wait(tmbar_s + 8u * bi, (uint32_t)((t / 3) & 1));
            float* eb = tiles + bi * HALF_FLOATS + plr * Sn;
            #pragma unroll
            for (int k = 0; k < 4; ++k) {
                float4* row = (float4*)(eb + k * Sn);
                #pragma unroll
                for (int c = 0; c < 4; ++c) {
                    float4 v = row[c * 32 + lane];
                    v.x = ex2f(v.x * LOG2E); v.y = ex2f(v.y * LOG2E);
                    v.z = ex2f(v.z * LOG2E); v.w = ex2f(v.w * LOG2E);
                    row[c * 32 + lane] = v;
                }
            }
            __syncwarp();
            if (lane == 0) mbar_arrive(er_s + 8u * (uint32_t)(t % 3));
        }
        // producers touch no phase-gated data after the loop; fall through
    }

    // teardown: no CTA exits while peers' s2s targeting it can be in flight.
    // Consumers arrive only after their drain; producers' arrival is harmless.
    asm volatile("barrier.cluster.arrive.aligned;" ::: "memory");
    asm volatile("barrier.cluster.wait.aligned;"   ::: "memory");
}

extern "C" void kernel_launch(void* const* d_in, const int* in_sizes, int n_in,
                              void* d_out, int out_size)
{
    const float* theta = (const float*)d_in[0];
    float* out = (float*)d_out;

    cudaFuncSetAttribute(viterbi_kernel,
                         cudaFuncAttributeMaxDynamicSharedMemorySize, SMEM_DYN);
    cudaFuncSetAttribute(viterbi_kernel,
                         cudaFuncAttributeNonPortableClusterSizeAllowed, 1);

    cudaLaunchConfig_t cfg = {};
    cfg.gridDim = dim3(Bn * CLUSTER, 1, 1);
    cfg.blockDim = dim3(NTHREADS, 1, 1);
    cfg.dynamicSmemBytes = SMEM_DYN;
    cfg.stream = 0;

    cudaLaunchAttribute attrs[1];
    attrs[0].id = cudaLaunchAttributeClusterDimension;
    attrs[0].val.clusterDim.x = CLUSTER;
    attrs[0].val.clusterDim.y = 1;
    attrs[0].val.clusterDim.z = 1;
    cfg.attrs = attrs;
    cfg.numAttrs = 1;

    cudaLaunchKernelEx(&cfg, viterbi_kernel, theta, out);
}